// round 3
// baseline (speedup 1.0000x reference)
#include <cuda_runtime.h>
#include <math.h>

#define FEAT 128
#define MAXN 20000

// Scratch (allocation-free rule: __device__ globals, referenced directly
// from kernels so kernel_launch contains ONLY kernel launches).
__device__ float g_hidden[MAXN * 128];
__device__ float g_phi[MAXN * 384];

__global__ void zero_kernel(float* __restrict__ out, int n) {
    int i  = blockIdx.x * blockDim.x + threadIdx.x;
    int i4 = i * 4;
    if (i4 + 3 < n) {
        *(float4*)(out + i4) = make_float4(0.f, 0.f, 0.f, 0.f);
    } else if (i4 < n) {
        for (int k = i4; k < n; k++) out[k] = 0.f;
    }
}

// C[M,N] = act(A[M,128] @ B[128,N] + bias), tile 64x128, K=128 fixed.
// MODE: 0 = A from g_hidden, write g_phi, no silu
//       1 = A from param,    write g_hidden, silu
template <int MODE>
__global__ __launch_bounds__(256)
void gemm_kernel(const float* __restrict__ Ain, const float* __restrict__ B,
                 const float* __restrict__ bias, int M, int N)
{
    const float* A = (MODE == 1) ? Ain : g_hidden;
    float*       C = (MODE == 1) ? g_hidden : g_phi;

    __shared__ float As[64][32];
    __shared__ float Bs[32][128];
    int tid  = threadIdx.x;
    int tcol = tid & 31;   // 32 thread-cols * 4 = 128 cols
    int trow = tid >> 5;   // 8 thread-rows * 8 = 64 rows
    int rowBase = blockIdx.x * 64;
    int colBase = blockIdx.y * 128;

    float acc[8][4];
#pragma unroll
    for (int i = 0; i < 8; i++)
#pragma unroll
        for (int j = 0; j < 4; j++) acc[i][j] = 0.f;

    for (int kt = 0; kt < 128; kt += 32) {
#pragma unroll
        for (int l = 0; l < 2; l++) {
            int idx = tid + l * 256;          // 512 float4s in A tile
            int r = idx >> 3, c4 = idx & 7;
            int gr = rowBase + r;
            float4 v = make_float4(0.f, 0.f, 0.f, 0.f);
            if (gr < M) v = *(const float4*)(A + (size_t)gr * 128 + kt + c4 * 4);
            *(float4*)&As[r][c4 * 4] = v;
        }
#pragma unroll
        for (int l = 0; l < 4; l++) {
            int idx = tid + l * 256;          // 1024 float4s in B tile
            int r = idx >> 5, c4 = idx & 31;
            *(float4*)&Bs[r][c4 * 4] =
                *(const float4*)(B + (size_t)(kt + r) * N + colBase + c4 * 4);
        }
        __syncthreads();
#pragma unroll
        for (int kk = 0; kk < 32; kk++) {
            float4 bv = *(const float4*)&Bs[kk][tcol * 4];
#pragma unroll
            for (int i = 0; i < 8; i++) {
                float av = As[trow * 8 + i][kk];
                acc[i][0] = fmaf(av, bv.x, acc[i][0]);
                acc[i][1] = fmaf(av, bv.y, acc[i][1]);
                acc[i][2] = fmaf(av, bv.z, acc[i][2]);
                acc[i][3] = fmaf(av, bv.w, acc[i][3]);
            }
        }
        __syncthreads();
    }

    float4 bb = *(const float4*)(bias + colBase + tcol * 4);
#pragma unroll
    for (int i = 0; i < 8; i++) {
        int gr = rowBase + trow * 8 + i;
        if (gr < M) {
            float4 o;
            o.x = acc[i][0] + bb.x;
            o.y = acc[i][1] + bb.y;
            o.z = acc[i][2] + bb.z;
            o.w = acc[i][3] + bb.w;
            if (MODE == 1) {
                o.x = o.x / (1.f + expf(-o.x));
                o.y = o.y / (1.f + expf(-o.y));
                o.z = o.z / (1.f + expf(-o.z));
                o.w = o.w / (1.f + expf(-o.w));
            }
            *(float4*)(C + (size_t)gr * N + colBase + tcol * 4) = o;
        }
    }
}

// One block = 128 edges; thread t owns feature f=t. Wd columns (f, 128+f, 256+f)
// live in 60 registers. RBF sines via Chebyshev recurrence fused into the dot.
__global__ __launch_bounds__(128, 4)
void edge_kernel(const float* __restrict__ r_ij, const int* __restrict__ nbw,
                 const float* __restrict__ vj,
                 const float* __restrict__ Wd, const float* __restrict__ bd,
                 float* __restrict__ out_s, float* __restrict__ out_v, int n_edges)
{
    __shared__ float4 sh_a[128];  // (sin x, 2 cos x, env, 1/d)
    __shared__ float4 sh_b[128];  // (ux, uy, uz, bitcast j)
    __shared__ int    sh_i[128];  // target node
    int t = threadIdx.x;

    // nbrs dtype sniff: int64 node ids < 20000 => high words zero.
    bool is64 = (nbw[1] == 0 && nbw[3] == 0 && nbw[5] == 0 && nbw[7] == 0);

    {   // cooperative per-edge setup: ONE sincosf per edge in the whole grid
        int e = blockIdx.x * 128 + t;
        float sx = 0.f, tc = 0.f, env = 0.f, invd = 0.f;
        float ux = 0.f, uy = 0.f, uz = 0.f;
        int inode = 0, jnode = 0;
        if (e < n_edges) {
            float x = r_ij[3 * e + 0], y = r_ij[3 * e + 1], z = r_ij[3 * e + 2];
            float d2 = x * x + y * y + z * z + 3e-15f;
            float d  = sqrtf(d2);
            invd = 1.0f / d;
            float cx;
            sincosf(d * 0.62831853071795864769f, &sx, &cx);   // x = pi*d/5
            env = (d < 5.0f) ? (0.5f * (cx + 1.0f)) : 0.0f;
            tc  = 2.0f * cx;
            ux = x * invd; uy = y * invd; uz = z * invd;
            if (is64) { inode = nbw[4 * e];     jnode = nbw[4 * e + 2]; }
            else      { inode = nbw[2 * e];     jnode = nbw[2 * e + 1]; }
        }
        sh_a[t] = make_float4(sx, tc, env, invd);
        sh_b[t] = make_float4(ux, uy, uz, __int_as_float(jnode));
        sh_i[t] = inode;
    }

    // Register-resident Wd columns for this feature (amortized over 128 edges)
    float wd0[20], wd1[20], wd2[20];
#pragma unroll
    for (int k = 0; k < 20; k++) {
        wd0[k] = Wd[k * 384 + t];
        wd1[k] = Wd[k * 384 + 128 + t];
        wd2[k] = Wd[k * 384 + 256 + t];
    }
    float bd0 = bd[t], bd1 = bd[128 + t], bd2 = bd[256 + t];
    __syncthreads();

    int nloc = min(128, n_edges - blockIdx.x * 128);
    for (int e = 0; e < nloc; e++) {
        float4 a = sh_a[e];
        float4 b = sh_b[e];
        int j     = __float_as_int(b.w);
        int inode = sh_i[e];

        const float* pp = g_phi + (size_t)j * 384 + t;  // coalesced, L2-resident
        float p0 = pp[0], p1 = pp[128], p2 = pp[256];
        const float* vp = vj + (size_t)j * 384 + 3 * t;
        float v0 = vp[0], v1 = vp[1], v2 = vp[2];

        // acc_c = sum_k sin((k+1)x) * Wd[k, c*128+f], sines via recurrence
        float a0 = 0.f, a1 = 0.f, a2 = 0.f;
        float sp = 0.f, sc = a.x;
#pragma unroll
        for (int k = 0; k < 20; k++) {
            a0 = fmaf(sc, wd0[k], a0);
            a1 = fmaf(sc, wd1[k], a1);
            a2 = fmaf(sc, wd2[k], a2);
            float sn = fmaf(a.y, sc, -sp);        // sin((k+2)x)
            sp = sc; sc = sn;
        }
        float w0 = fmaf(a0, a.w, bd0) * a.z;      // (acc/d + bd) * env
        float w1 = fmaf(a1, a.w, bd1) * a.z;
        float w2 = fmaf(a2, a.w, bd2) * a.z;

        float s0 = p0 * w0;   // scales v_j
        float s1 = p1 * w1;   // delta_s
        float s2 = p2 * w2;   // scales unit

        atomicAdd(out_s + (size_t)inode * 128 + t, s1);
        float* ov = out_v + (size_t)inode * 384 + 3 * t;
        atomicAdd(ov + 0, fmaf(s2, b.x, s0 * v0));
        atomicAdd(ov + 1, fmaf(s2, b.y, s0 * v1));
        atomicAdd(ov + 2, fmaf(s2, b.z, s0 * v2));
    }
}

extern "C" void kernel_launch(void* const* d_in, const int* in_sizes, int n_in,
                              void* d_out, int out_size) {
    const float* s_j  = (const float*)d_in[0];
    const float* v_j  = (const float*)d_in[1];
    const float* r_ij = (const float*)d_in[2];
    const int*   nbrs = (const int*)d_in[3];   // dtype sniffed device-side
    const float* W1 = (const float*)d_in[4];
    const float* b1 = (const float*)d_in[5];
    const float* W2 = (const float*)d_in[6];
    const float* b2 = (const float*)d_in[7];
    const float* Wd = (const float*)d_in[8];
    const float* bd = (const float*)d_in[9];
    float* out = (float*)d_out;

    int n_nodes = in_sizes[0] / FEAT;
    int n_edges = in_sizes[2] / 3;

    int n4blocks = ((out_size + 3) / 4 + 255) / 256;
    zero_kernel<<<n4blocks, 256>>>(out, out_size);

    dim3 g1((n_nodes + 63) / 64, 1);
    gemm_kernel<1><<<g1, 256>>>(s_j, W1, b1, n_nodes, 128);
    dim3 g2((n_nodes + 63) / 64, 3);
    gemm_kernel<0><<<g2, 256>>>(nullptr, W2, b2, n_nodes, 384);

    int eblocks = (n_edges + 127) / 128;
    edge_kernel<<<eblocks, 128>>>(r_ij, nbrs, v_j, Wd, bd,
                                  out, out + (size_t)n_nodes * FEAT, n_edges);
}

// round 4
// speedup vs baseline: 1.0192x; 1.0192x over previous
#include <cuda_runtime.h>
#include <math.h>

#define FEAT 128
#define MAXN 20000
#define MAXE 640000

// Scratch (allocation-free rule: __device__ globals, referenced directly
// from kernels so kernel_launch contains ONLY kernel launches).
__device__ float  g_hidden[MAXN * 128];
__device__ float  g_phi[MAXN * 384];
__device__ int    g_cntraw[MAXN];
__device__ int    g_row[MAXN + 1];
__device__ int    g_cur[MAXN];
__device__ float4 g_ea[MAXE];   // (sin x, 2 cos x, env, 1/d)
__device__ float4 g_eb[MAXE];   // (ux, uy, uz, bitcast j)

__global__ void zero_cnt_kernel(int n) {
    int i = blockIdx.x * blockDim.x + threadIdx.x;
    if (i < n) g_cntraw[i] = 0;
}

__device__ __forceinline__ bool sniff64(const int* __restrict__ nbw) {
    // int64 node ids < 20000 => high words zero.
    return (nbw[1] == 0 && nbw[3] == 0 && nbw[5] == 0 && nbw[7] == 0);
}

__global__ void count_kernel(const int* __restrict__ nbw, int n_edges) {
    int e = blockIdx.x * blockDim.x + threadIdx.x;
    if (e >= n_edges) return;
    bool is64 = sniff64(nbw);
    int i = is64 ? nbw[4 * e] : nbw[2 * e];
    atomicAdd(&g_cntraw[i], 1);
}

// Single-block exclusive scan over n_nodes bins -> g_row (starts) + g_cur (cursors)
__global__ __launch_bounds__(1024)
void scan_kernel(int n_nodes) {
    __shared__ int part[1024];
    int t = threadIdx.x;
    int per = (n_nodes + 1023) / 1024;
    int base = t * per;
    int s = 0;
    for (int k = 0; k < per; k++) {
        int idx = base + k;
        if (idx < n_nodes) s += g_cntraw[idx];
    }
    part[t] = s;
    __syncthreads();
    for (int off = 1; off < 1024; off <<= 1) {
        int v = (t >= off) ? part[t - off] : 0;
        __syncthreads();
        part[t] += v;
        __syncthreads();
    }
    int run = (t == 0) ? 0 : part[t - 1];
    for (int k = 0; k < per; k++) {
        int idx = base + k;
        if (idx < n_nodes) {
            int c = g_cntraw[idx];
            g_row[idx] = run;
            g_cur[idx] = run;
            run += c;
        }
    }
    if (t == 1023) g_row[n_nodes] = run;
}

// Per-edge geometry precompute + scatter directly into sorted slot.
__global__ void scatter_kernel(const float* __restrict__ r_ij,
                               const int* __restrict__ nbw, int n_edges) {
    int e = blockIdx.x * blockDim.x + threadIdx.x;
    if (e >= n_edges) return;
    bool is64 = sniff64(nbw);
    int inode, jnode;
    if (is64) { inode = nbw[4 * e]; jnode = nbw[4 * e + 2]; }
    else      { inode = nbw[2 * e]; jnode = nbw[2 * e + 1]; }

    float x = r_ij[3 * e + 0], y = r_ij[3 * e + 1], z = r_ij[3 * e + 2];
    float d2 = x * x + y * y + z * z + 3e-15f;
    float d  = sqrtf(d2);
    float invd = 1.0f / d;
    float sx, cx;
    sincosf(d * 0.62831853071795864769f, &sx, &cx);    // pi*d/5
    float env = (d < 5.0f) ? (0.5f * (cx + 1.0f)) : 0.0f;
    float tc  = 2.0f * cx;

    int pos = atomicAdd(&g_cur[inode], 1);
    g_ea[pos] = make_float4(sx, tc, env, invd);
    g_eb[pos] = make_float4(x * invd, y * invd, z * invd, __int_as_float(jnode));
}

// C[M,N] = act(A[M,128] @ B[128,N] + bias), tile 64x128, K=128 fixed.
// MODE: 1 = A param -> g_hidden with silu; 0 = g_hidden -> g_phi, no silu
template <int MODE>
__global__ __launch_bounds__(256)
void gemm_kernel(const float* __restrict__ Ain, const float* __restrict__ B,
                 const float* __restrict__ bias, int M, int N)
{
    const float* A = (MODE == 1) ? Ain : g_hidden;
    float*       C = (MODE == 1) ? g_hidden : g_phi;

    __shared__ float As[64][32];
    __shared__ float Bs[32][128];
    int tid  = threadIdx.x;
    int tcol = tid & 31;
    int trow = tid >> 5;
    int rowBase = blockIdx.x * 64;
    int colBase = blockIdx.y * 128;

    float acc[8][4];
#pragma unroll
    for (int i = 0; i < 8; i++)
#pragma unroll
        for (int j = 0; j < 4; j++) acc[i][j] = 0.f;

    for (int kt = 0; kt < 128; kt += 32) {
#pragma unroll
        for (int l = 0; l < 2; l++) {
            int idx = tid + l * 256;
            int r = idx >> 3, c4 = idx & 7;
            int gr = rowBase + r;
            float4 v = make_float4(0.f, 0.f, 0.f, 0.f);
            if (gr < M) v = *(const float4*)(A + (size_t)gr * 128 + kt + c4 * 4);
            *(float4*)&As[r][c4 * 4] = v;
        }
#pragma unroll
        for (int l = 0; l < 4; l++) {
            int idx = tid + l * 256;
            int r = idx >> 5, c4 = idx & 31;
            *(float4*)&Bs[r][c4 * 4] =
                *(const float4*)(B + (size_t)(kt + r) * N + colBase + c4 * 4);
        }
        __syncthreads();
#pragma unroll
        for (int kk = 0; kk < 32; kk++) {
            float4 bv = *(const float4*)&Bs[kk][tcol * 4];
#pragma unroll
            for (int i = 0; i < 8; i++) {
                float av = As[trow * 8 + i][kk];
                acc[i][0] = fmaf(av, bv.x, acc[i][0]);
                acc[i][1] = fmaf(av, bv.y, acc[i][1]);
                acc[i][2] = fmaf(av, bv.z, acc[i][2]);
                acc[i][3] = fmaf(av, bv.w, acc[i][3]);
            }
        }
        __syncthreads();
    }

    float4 bb = *(const float4*)(bias + colBase + tcol * 4);
#pragma unroll
    for (int i = 0; i < 8; i++) {
        int gr = rowBase + trow * 8 + i;
        if (gr < M) {
            float4 o;
            o.x = acc[i][0] + bb.x;
            o.y = acc[i][1] + bb.y;
            o.z = acc[i][2] + bb.z;
            o.w = acc[i][3] + bb.w;
            if (MODE == 1) {
                o.x = o.x / (1.f + expf(-o.x));
                o.y = o.y / (1.f + expf(-o.y));
                o.z = o.z / (1.f + expf(-o.z));
                o.w = o.w / (1.f + expf(-o.w));
            }
            *(float4*)(C + (size_t)gr * N + colBase + tcol * 4) = o;
        }
    }
}

// One block per node; thread t owns feature f=t. Accumulate the node's whole
// segment in registers, single store at the end. NO output atomics.
__global__ __launch_bounds__(128, 4)
void gather_kernel(const float* __restrict__ vj,
                   const float* __restrict__ Wd, const float* __restrict__ bd,
                   float* __restrict__ out_s, float* __restrict__ out_v)
{
    __shared__ float4 sh_a[128];
    __shared__ float4 sh_b[128];
    int i = blockIdx.x;
    int t = threadIdx.x;
    int start = g_row[i];
    int end   = g_row[i + 1];

    // Register-resident Wd columns for this feature
    float wd0[20], wd1[20], wd2[20];
#pragma unroll
    for (int k = 0; k < 20; k++) {
        wd0[k] = Wd[k * 384 + t];
        wd1[k] = Wd[k * 384 + 128 + t];
        wd2[k] = Wd[k * 384 + 256 + t];
    }
    float bd0 = bd[t], bd1 = bd[128 + t], bd2 = bd[256 + t];

    float acc_s = 0.f, av0 = 0.f, av1 = 0.f, av2 = 0.f;

    for (int base = start; base < end; base += 128) {
        int chunk = min(128, end - base);
        __syncthreads();
        if (t < chunk) {
            sh_a[t] = g_ea[base + t];
            sh_b[t] = g_eb[base + t];
        }
        __syncthreads();

        for (int e = 0; e < chunk; e++) {
            float4 a = sh_a[e];
            float4 b = sh_b[e];
            int j = __float_as_int(b.w);

            const float* pp = g_phi + (size_t)j * 384 + t;   // L2-resident, coalesced
            float p0 = pp[0], p1 = pp[128], p2 = pp[256];
            const float* vp = vj + (size_t)j * 384 + 3 * t;
            float v0 = vp[0], v1 = vp[1], v2 = vp[2];

            // acc_c = sum_k sin((k+1)x) * Wd[k, c*128+f]; sines via recurrence
            float a0 = 0.f, a1 = 0.f, a2 = 0.f;
            float sp = 0.f, sc = a.x;
#pragma unroll
            for (int k = 0; k < 20; k++) {
                a0 = fmaf(sc, wd0[k], a0);
                a1 = fmaf(sc, wd1[k], a1);
                a2 = fmaf(sc, wd2[k], a2);
                float sn = fmaf(a.y, sc, -sp);
                sp = sc; sc = sn;
            }
            float w0 = fmaf(a0, a.w, bd0) * a.z;
            float w1 = fmaf(a1, a.w, bd1) * a.z;
            float w2 = fmaf(a2, a.w, bd2) * a.z;

            float s0 = p0 * w0;     // scales v_j
            float s2 = p2 * w2;     // scales unit
            acc_s = fmaf(p1, w1, acc_s);
            av0 = fmaf(s2, b.x, fmaf(s0, v0, av0));
            av1 = fmaf(s2, b.y, fmaf(s0, v1, av1));
            av2 = fmaf(s2, b.z, fmaf(s0, v2, av2));
        }
    }

    out_s[(size_t)i * 128 + t] = acc_s;
    float* ov = out_v + (size_t)i * 384 + 3 * t;
    ov[0] = av0; ov[1] = av1; ov[2] = av2;
}

extern "C" void kernel_launch(void* const* d_in, const int* in_sizes, int n_in,
                              void* d_out, int out_size) {
    const float* s_j  = (const float*)d_in[0];
    const float* v_j  = (const float*)d_in[1];
    const float* r_ij = (const float*)d_in[2];
    const int*   nbrs = (const int*)d_in[3];   // dtype sniffed device-side
    const float* W1 = (const float*)d_in[4];
    const float* b1 = (const float*)d_in[5];
    const float* W2 = (const float*)d_in[6];
    const float* b2 = (const float*)d_in[7];
    const float* Wd = (const float*)d_in[8];
    const float* bd = (const float*)d_in[9];
    float* out = (float*)d_out;

    int n_nodes = in_sizes[0] / FEAT;
    int n_edges = in_sizes[2] / 3;

    // CSR build
    zero_cnt_kernel<<<(n_nodes + 255) / 256, 256>>>(n_nodes);
    count_kernel<<<(n_edges + 255) / 256, 256>>>(nbrs, n_edges);
    scan_kernel<<<1, 1024>>>(n_nodes);
    scatter_kernel<<<(n_edges + 255) / 256, 256>>>(r_ij, nbrs, n_edges);

    // Node GEMMs
    dim3 g1((n_nodes + 63) / 64, 1);
    gemm_kernel<1><<<g1, 256>>>(s_j, W1, b1, n_nodes, 128);
    dim3 g2((n_nodes + 63) / 64, 3);
    gemm_kernel<0><<<g2, 256>>>(nullptr, W2, b2, n_nodes, 384);

    // Atomic-free gather
    gather_kernel<<<n_nodes, 128>>>(v_j, Wd, bd,
                                    out, out + (size_t)n_nodes * FEAT);
}

// round 5
// speedup vs baseline: 1.1808x; 1.1585x over previous
#include <cuda_runtime.h>
#include <math.h>

#define FEAT 128
#define MAXN 20000
#define MAXE 640000

// Scratch (allocation-free rule: __device__ globals).
__device__ float  g_hidden[MAXN * 128];
__device__ float  g_phi[MAXN * 384];
__device__ int    g_cntraw[MAXN];
__device__ int    g_row[MAXN + 1];
__device__ int    g_cur[MAXN];
__device__ float4 g_ea[MAXE];   // (sin x, 2 cos x, env, 1/d)
__device__ float4 g_eb[MAXE];   // (ux, uy, uz, bitcast j)
__device__ int    g_ei[MAXE];   // target node of sorted edge

// ---- f32x2 packed helpers (FFMA2 is PTX-only; see SASS quickref) ----
__device__ __forceinline__ unsigned long long pk2(float lo, float hi) {
    unsigned long long r;
    asm("mov.b64 %0, {%1, %2};" : "=l"(r) : "f"(lo), "f"(hi));
    return r;
}
__device__ __forceinline__ void upk2(float& lo, float& hi, unsigned long long v) {
    asm("mov.b64 {%0, %1}, %2;" : "=f"(lo), "=f"(hi) : "l"(v));
}
#define FMA2(d, a, b, c) \
    asm("fma.rn.f32x2 %0, %1, %2, %3;" : "=l"(d) : "l"(a), "l"(b), "l"(c))

__global__ void zero_out_kernel(float* __restrict__ out, int n) {
    int i  = blockIdx.x * blockDim.x + threadIdx.x;
    int i4 = i * 4;
    if (i4 + 3 < n) {
        *(float4*)(out + i4) = make_float4(0.f, 0.f, 0.f, 0.f);
    } else if (i4 < n) {
        for (int k = i4; k < n; k++) out[k] = 0.f;
    }
}

__global__ void zero_cnt_kernel(int n) {
    int i = blockIdx.x * blockDim.x + threadIdx.x;
    if (i < n) g_cntraw[i] = 0;
}

__device__ __forceinline__ bool sniff64(const int* __restrict__ nbw) {
    // int64 node ids < 20000 => high words zero.
    return (nbw[1] == 0 && nbw[3] == 0 && nbw[5] == 0 && nbw[7] == 0);
}

__global__ void count_kernel(const int* __restrict__ nbw, int n_edges) {
    int e = blockIdx.x * blockDim.x + threadIdx.x;
    if (e >= n_edges) return;
    bool is64 = sniff64(nbw);
    int i = is64 ? nbw[4 * e] : nbw[2 * e];
    atomicAdd(&g_cntraw[i], 1);
}

// Single-block exclusive scan over n_nodes bins -> g_row + cursors
__global__ __launch_bounds__(1024)
void scan_kernel(int n_nodes) {
    __shared__ int part[1024];
    int t = threadIdx.x;
    int per = (n_nodes + 1023) / 1024;
    int base = t * per;
    int s = 0;
    for (int k = 0; k < per; k++) {
        int idx = base + k;
        if (idx < n_nodes) s += g_cntraw[idx];
    }
    part[t] = s;
    __syncthreads();
    for (int off = 1; off < 1024; off <<= 1) {
        int v = (t >= off) ? part[t - off] : 0;
        __syncthreads();
        part[t] += v;
        __syncthreads();
    }
    int run = (t == 0) ? 0 : part[t - 1];
    for (int k = 0; k < per; k++) {
        int idx = base + k;
        if (idx < n_nodes) {
            int c = g_cntraw[idx];
            g_row[idx] = run;
            g_cur[idx] = run;
            run += c;
        }
    }
    if (t == 1023) g_row[n_nodes] = run;
}

// Per-edge geometry precompute + scatter into sorted slot.
__global__ void scatter_kernel(const float* __restrict__ r_ij,
                               const int* __restrict__ nbw, int n_edges) {
    int e = blockIdx.x * blockDim.x + threadIdx.x;
    if (e >= n_edges) return;
    bool is64 = sniff64(nbw);
    int inode, jnode;
    if (is64) { inode = nbw[4 * e]; jnode = nbw[4 * e + 2]; }
    else      { inode = nbw[2 * e]; jnode = nbw[2 * e + 1]; }

    float x = r_ij[3 * e + 0], y = r_ij[3 * e + 1], z = r_ij[3 * e + 2];
    float d2 = x * x + y * y + z * z + 3e-15f;
    float d  = sqrtf(d2);
    float invd = 1.0f / d;
    float sx, cx;
    sincosf(d * 0.62831853071795864769f, &sx, &cx);    // pi*d/5
    float env = (d < 5.0f) ? (0.5f * (cx + 1.0f)) : 0.0f;
    float tc  = 2.0f * cx;

    int pos = atomicAdd(&g_cur[inode], 1);
    g_ea[pos] = make_float4(sx, tc, env, invd);
    g_eb[pos] = make_float4(x * invd, y * invd, z * invd, __int_as_float(jnode));
    g_ei[pos] = inode;
}

// C[M,N] = act(A[M,128] @ B[128,N] + bias), tile 64x128, K=128 fixed.
template <int MODE>   // 1: A param -> g_hidden, silu; 0: g_hidden -> g_phi
__global__ __launch_bounds__(256)
void gemm_kernel(const float* __restrict__ Ain, const float* __restrict__ B,
                 const float* __restrict__ bias, int M, int N)
{
    const float* A = (MODE == 1) ? Ain : g_hidden;
    float*       C = (MODE == 1) ? g_hidden : g_phi;

    __shared__ float As[64][32];
    __shared__ float Bs[32][128];
    int tid  = threadIdx.x;
    int tcol = tid & 31;
    int trow = tid >> 5;
    int rowBase = blockIdx.x * 64;
    int colBase = blockIdx.y * 128;

    float acc[8][4];
#pragma unroll
    for (int i = 0; i < 8; i++)
#pragma unroll
        for (int j = 0; j < 4; j++) acc[i][j] = 0.f;

    for (int kt = 0; kt < 128; kt += 32) {
#pragma unroll
        for (int l = 0; l < 2; l++) {
            int idx = tid + l * 256;
            int r = idx >> 3, c4 = idx & 7;
            int gr = rowBase + r;
            float4 v = make_float4(0.f, 0.f, 0.f, 0.f);
            if (gr < M) v = *(const float4*)(A + (size_t)gr * 128 + kt + c4 * 4);
            *(float4*)&As[r][c4 * 4] = v;
        }
#pragma unroll
        for (int l = 0; l < 4; l++) {
            int idx = tid + l * 256;
            int r = idx >> 5, c4 = idx & 31;
            *(float4*)&Bs[r][c4 * 4] =
                *(const float4*)(B + (size_t)(kt + r) * N + colBase + c4 * 4);
        }
        __syncthreads();
#pragma unroll
        for (int kk = 0; kk < 32; kk++) {
            float4 bv = *(const float4*)&Bs[kk][tcol * 4];
#pragma unroll
            for (int i = 0; i < 8; i++) {
                float av = As[trow * 8 + i][kk];
                acc[i][0] = fmaf(av, bv.x, acc[i][0]);
                acc[i][1] = fmaf(av, bv.y, acc[i][1]);
                acc[i][2] = fmaf(av, bv.z, acc[i][2]);
                acc[i][3] = fmaf(av, bv.w, acc[i][3]);
            }
        }
        __syncthreads();
    }

    float4 bb = *(const float4*)(bias + colBase + tcol * 4);
#pragma unroll
    for (int i = 0; i < 8; i++) {
        int gr = rowBase + trow * 8 + i;
        if (gr < M) {
            float4 o;
            o.x = acc[i][0] + bb.x;
            o.y = acc[i][1] + bb.y;
            o.z = acc[i][2] + bb.z;
            o.w = acc[i][3] + bb.w;
            if (MODE == 1) {
                o.x = o.x / (1.f + expf(-o.x));
                o.y = o.y / (1.f + expf(-o.y));
                o.z = o.z / (1.f + expf(-o.z));
                o.w = o.w / (1.f + expf(-o.w));
            }
            *(float4*)(C + (size_t)gr * N + colBase + tcol * 4) = o;
        }
    }
}

// Block = 128 sorted edges; thread t owns feature t. Sines hoisted (computed
// once per edge in prologue, pre-scaled by env/d, stored DUPLICATED so the
// k-loop reads ready-made f32x2 operands). Channel pair (c0,c1) via FFMA2.
// Register accumulation, flushed by atomicAdd only on node change.
__global__ __launch_bounds__(128, 4)
void gather_kernel(const float* __restrict__ vj,
                   const float* __restrict__ Wd, const float* __restrict__ bd,
                   float* __restrict__ out_s, float* __restrict__ out_v,
                   int n_edges)
{
    __shared__ float  sh_t[128][44];   // 20 duplicated pairs (40 used), pad->176B row
    __shared__ float4 sh_u[128];       // (ux, uy, uz, bitcast j)
    __shared__ float  sh_env[128];
    __shared__ int    sh_node[128];

    int t = threadIdx.x;
    int base = blockIdx.x * 128;
    int chunk = min(128, n_edges - base);

    // Register-resident Wd for this feature, (c0,c1) packed
    unsigned long long wd01[20];
    float wd2[20];
#pragma unroll
    for (int k = 0; k < 20; k++) {
        wd01[k] = pk2(Wd[k * 384 + t], Wd[k * 384 + 128 + t]);
        wd2[k]  = Wd[k * 384 + 256 + t];
    }
    unsigned long long bd01 = pk2(bd[t], bd[128 + t]);
    float bd2 = bd[256 + t];

    // Prologue: stage edge records + per-edge sine table (one edge per thread)
    if (t < chunk) {
        float4 a = g_ea[base + t];     // (sin x, 2 cos x, env, 1/d)
        float  scale = a.z * a.w;      // env / d  (folds into every rbf term)
        float  sp = 0.f, sc = a.x;
#pragma unroll
        for (int k = 0; k < 20; k++) {
            float tv = sc * scale;
            sh_t[t][2 * k]     = tv;
            sh_t[t][2 * k + 1] = tv;
            float sn = fmaf(a.y, sc, -sp);
            sp = sc; sc = sn;
        }
        sh_u[t]    = g_eb[base + t];
        sh_env[t]  = a.z;
        sh_node[t] = g_ei[base + t];
    }
    __syncthreads();

    float acc_s = 0.f, av0 = 0.f, av1 = 0.f, av2 = 0.f;
    int cur = -1;

    for (int e = 0; e < chunk; e++) {
        int node = sh_node[e];
        if (node != cur) {                     // uniform branch across block
            if (cur >= 0) {
                atomicAdd(out_s + (size_t)cur * 128 + t, acc_s);
                float* ov = out_v + (size_t)cur * 384 + 3 * t;
                atomicAdd(ov + 0, av0);
                atomicAdd(ov + 1, av1);
                atomicAdd(ov + 2, av2);
            }
            cur = node;
            acc_s = av0 = av1 = av2 = 0.f;
        }

        float4 u = sh_u[e];
        int j = __float_as_int(u.w);
        const float* pp = g_phi + (size_t)j * 384 + t;   // L2-resident, coalesced
        float p0 = pp[0], p1 = pp[128], p2 = pp[256];
        const float* vp = vj + (size_t)j * 384 + 3 * t;
        float v0 = vp[0], v1 = vp[1], v2 = vp[2];

        unsigned long long a01 = 0ULL;   // packed (0,0)
        float a2 = 0.f;
        const float4* row = (const float4*)sh_t[e];
#pragma unroll
        for (int m = 0; m < 10; m++) {
            float4 q = row[m];           // (t_2m, t_2m, t_2m+1, t_2m+1)
            unsigned long long qlo = pk2(q.x, q.y);
            unsigned long long qhi = pk2(q.z, q.w);
            FMA2(a01, qlo, wd01[2 * m], a01);
            a2 = fmaf(q.x, wd2[2 * m], a2);
            FMA2(a01, qhi, wd01[2 * m + 1], a01);
            a2 = fmaf(q.z, wd2[2 * m + 1], a2);
        }
        float env = sh_env[e];
        unsigned long long envp = pk2(env, env);
        unsigned long long w01;
        FMA2(w01, bd01, envp, a01);      // w_c = acc_c + bd_c*env
        float w0, w1;
        upk2(w0, w1, w01);
        float w2 = fmaf(bd2, env, a2);

        float s0 = p0 * w0;              // scales v_j
        float s2 = p2 * w2;              // scales unit
        acc_s = fmaf(p1, w1, acc_s);
        av0 = fmaf(s2, u.x, fmaf(s0, v0, av0));
        av1 = fmaf(s2, u.y, fmaf(s0, v1, av1));
        av2 = fmaf(s2, u.z, fmaf(s0, v2, av2));
    }

    if (cur >= 0) {
        atomicAdd(out_s + (size_t)cur * 128 + t, acc_s);
        float* ov = out_v + (size_t)cur * 384 + 3 * t;
        atomicAdd(ov + 0, av0);
        atomicAdd(ov + 1, av1);
        atomicAdd(ov + 2, av2);
    }
}

extern "C" void kernel_launch(void* const* d_in, const int* in_sizes, int n_in,
                              void* d_out, int out_size) {
    const float* s_j  = (const float*)d_in[0];
    const float* v_j  = (const float*)d_in[1];
    const float* r_ij = (const float*)d_in[2];
    const int*   nbrs = (const int*)d_in[3];   // dtype sniffed device-side
    const float* W1 = (const float*)d_in[4];
    const float* b1 = (const float*)d_in[5];
    const float* W2 = (const float*)d_in[6];
    const float* b2 = (const float*)d_in[7];
    const float* Wd = (const float*)d_in[8];
    const float* bd = (const float*)d_in[9];
    float* out = (float*)d_out;

    int n_nodes = in_sizes[0] / FEAT;
    int n_edges = in_sizes[2] / 3;

    // Output zero (gather flushes via atomics)
    int n4blocks = ((out_size + 3) / 4 + 255) / 256;
    zero_out_kernel<<<n4blocks, 256>>>(out, out_size);

    // CSR build
    zero_cnt_kernel<<<(n_nodes + 255) / 256, 256>>>(n_nodes);
    count_kernel<<<(n_edges + 255) / 256, 256>>>(nbrs, n_edges);
    scan_kernel<<<1, 1024>>>(n_nodes);
    scatter_kernel<<<(n_edges + 255) / 256, 256>>>(r_ij, nbrs, n_edges);

    // Node GEMMs
    dim3 g1((n_nodes + 63) / 64, 1);
    gemm_kernel<1><<<g1, 256>>>(s_j, W1, b1, n_nodes, 128);
    dim3 g2((n_nodes + 63) / 64, 3);
    gemm_kernel<0><<<g2, 256>>>(nullptr, W2, b2, n_nodes, 384);

    // FFMA2 gather over sorted edges
    int eblocks = (n_edges + 127) / 128;
    gather_kernel<<<eblocks, 128>>>(v_j, Wd, bd,
                                    out, out + (size_t)n_nodes * FEAT, n_edges);
}